// round 5
// baseline (speedup 1.0000x reference)
#include <cuda_runtime.h>
#include <cuda_bf16.h>
#include <cstdint>

#define N_NODES 100000
#define N_EDGES 800000
#define D_IN    256      // 64 + 64 + 128
#define D_OUT   128

#define KPAD    264      // padded k-stride in bf16 elems (132 words)
#define W_IMG_HALF  67584    // 128 rows * 264 bf16 * 2B
#define W_IMG_TOTAL 135168   // hi + lo

// Aggregation buffer only: [N_NODES][128] = [agg_a(0:64) | agg_b(64:128)].
// Zero at module load (BSS); gemm kernel re-zeroes its tile after consuming it,
// so the zero-before-scatter invariant holds for every replay.
__device__ __align__(16) float g_x[(size_t)N_NODES * 128];

// W^T split images: [n=128][k=264(padded)] bf16, hi at 0, lo at W_IMG_HALF
__device__ __align__(16) unsigned char g_wt[W_IMG_TOTAL];

// ---------------------------------------------------------------------------
// Kernel 0: split W into bf16 hi/lo, transposed into padded image.
// ---------------------------------------------------------------------------
__global__ void prep_w_kernel(const float* __restrict__ W) {
    int idx = blockIdx.x * blockDim.x + threadIdx.x;   // 0 .. 32767
    if (idx >= D_IN * D_OUT) return;
    int n = idx & 127;          // output col  -> B row
    int k = idx >> 7;           // input  dim  -> B col
    float w = W[k * D_OUT + n];
    __nv_bfloat16 h = __float2bfloat16_rn(w);
    __nv_bfloat16 l = __float2bfloat16_rn(w - __bfloat162float(h));
    uint32_t off = (uint32_t)n * (KPAD * 2) + (uint32_t)k * 2;
    *(__nv_bfloat16*)(g_wt + off)              = h;
    *(__nv_bfloat16*)(g_wt + W_IMG_HALF + off) = l;
}

// ---------------------------------------------------------------------------
// Kernel 1: fused scatter-add for both edge types via red.global.add.v4.f32.
// idx < N_EDGES*16 -> type a (cols 0:64); else type b (cols 64:128).
// ---------------------------------------------------------------------------
__global__ void scatter2_kernel(const float* __restrict__ edata_a,
                                const int* __restrict__ recv_a,
                                const float* __restrict__ edata_b,
                                const int* __restrict__ recv_b) {
    int idx = blockIdx.x * blockDim.x + threadIdx.x;   // 0 .. 25.6M-1
    const int half = N_EDGES * 16;
    bool isB = idx >= half;
    int i = isB ? idx - half : idx;
    const float* e = isB ? edata_b : edata_a;
    const int*   rv = isB ? recv_b  : recv_a;
    int edge = i >> 4;
    int q    = i & 15;
    float4 v = reinterpret_cast<const float4*>(e)[(size_t)edge * 16 + q];
    int r = rv[edge];
    float* dst = g_x + (size_t)r * 128 + (isB ? 64 : 0) + q * 4;
    asm volatile("red.global.add.v4.f32 [%0], {%1, %2, %3, %4};"
                 :: "l"(dst), "f"(v.x), "f"(v.y), "f"(v.z), "f"(v.w)
                 : "memory");
}

// ---------------------------------------------------------------------------
// mma.sync bf16 helper (baseline PTX, HMMA pipe)
// ---------------------------------------------------------------------------
__device__ __forceinline__ void mma_bf16(float* d, const uint32_t* a,
                                         const uint32_t* b) {
    asm volatile(
        "mma.sync.aligned.m16n8k16.row.col.f32.bf16.bf16.f32 "
        "{%0,%1,%2,%3}, {%4,%5,%6,%7}, {%8,%9}, {%0,%1,%2,%3};"
        : "+f"(d[0]), "+f"(d[1]), "+f"(d[2]), "+f"(d[3])
        : "r"(a[0]), "r"(a[1]), "r"(a[2]), "r"(a[3]),
          "r"(b[0]), "r"(b[1]));
}

// SMEM layout (uint32 words)
#define SW_H 0
#define SW_L 16896
#define SX_H 33792
#define SX_L 42240
#define SMEM_WORDS 50688     // 202752 bytes

// ---------------------------------------------------------------------------
// Kernel 2: HMMA GEMM, split-bf16: out = [agg | vdata] @ W + b.
// Also re-zeroes its g_x tile after staging (restores invariant for next call).
// 256 threads / 8 warps. M_TILE = 64. Warp tile = 16(M) x 64(N).
// ---------------------------------------------------------------------------
__global__ __launch_bounds__(256, 1)
void gemm_mma_kernel(const float* __restrict__ vdata,
                     const float* __restrict__ bias,
                     float* __restrict__ out) {
    extern __shared__ uint32_t smem[];
    const int tid  = threadIdx.x;
    const int wid  = tid >> 5;
    const int lane = tid & 31;
    const int grp  = lane >> 2;       // 0..7
    const int qp   = lane & 3;        // 0..3
    const int node0 = blockIdx.x * 64;

    const int m0 = (wid & 3) * 16;    // warp M band within tile
    const int n0 = (wid >> 2) * 64;   // warp N half

    // ---- Stage W^T image (hi+lo, 135168B = 8448 uint4) ----
    {
        const uint4* src = reinterpret_cast<const uint4*>(g_wt);
        uint4* dst = reinterpret_cast<uint4*>(smem);
        #pragma unroll
        for (int i = 0; i < 33; i++) dst[i * 256 + tid] = src[i * 256 + tid];
    }

    // ---- Stage x tile: agg from g_x (cols 0:128) + vdata (cols 128:256),
    //      split into bf16 hi/lo with padded rows ----
    {
        const float4* A4 = reinterpret_cast<const float4*>(g_x);
        const float4* V4 = reinterpret_cast<const float4*>(vdata);
        #pragma unroll
        for (int i = 0; i < 16; i++) {
            int j  = i * 256 + tid;     // 0..4095
            int r  = j >> 6;            // tile row 0..63
            int c4 = j & 63;            // float4 idx in row
            int node = node0 + r;
            float4 v = make_float4(0.f, 0.f, 0.f, 0.f);
            if (node < N_NODES)
                v = (c4 < 32) ? A4[(size_t)node * 32 + c4]
                              : V4[(size_t)node * 32 + (c4 - 32)];
            __nv_bfloat16 h0 = __float2bfloat16_rn(v.x);
            __nv_bfloat16 h1 = __float2bfloat16_rn(v.y);
            __nv_bfloat16 h2 = __float2bfloat16_rn(v.z);
            __nv_bfloat16 h3 = __float2bfloat16_rn(v.w);
            __nv_bfloat16 l0 = __float2bfloat16_rn(v.x - __bfloat162float(h0));
            __nv_bfloat16 l1 = __float2bfloat16_rn(v.y - __bfloat162float(h1));
            __nv_bfloat16 l2 = __float2bfloat16_rn(v.z - __bfloat162float(h2));
            __nv_bfloat16 l3 = __float2bfloat16_rn(v.w - __bfloat162float(h3));
            uint32_t hi01 = ((uint32_t)__bfloat16_as_ushort(h1) << 16) | __bfloat16_as_ushort(h0);
            uint32_t hi23 = ((uint32_t)__bfloat16_as_ushort(h3) << 16) | __bfloat16_as_ushort(h2);
            uint32_t lo01 = ((uint32_t)__bfloat16_as_ushort(l1) << 16) | __bfloat16_as_ushort(l0);
            uint32_t lo23 = ((uint32_t)__bfloat16_as_ushort(l3) << 16) | __bfloat16_as_ushort(l2);
            int wbase = r * 132 + c4 * 2;
            smem[SX_H + wbase]     = hi01;
            smem[SX_H + wbase + 1] = hi23;
            smem[SX_L + wbase]     = lo01;
            smem[SX_L + wbase + 1] = lo23;
        }
    }
    __syncthreads();

    // ---- Re-zero this tile's agg region (overlaps with compute below) ----
    {
        float4 z = make_float4(0.f, 0.f, 0.f, 0.f);
        float4* A4 = reinterpret_cast<float4*>(g_x);
        #pragma unroll
        for (int i = 0; i < 8; i++) {
            int j  = i * 256 + tid;     // 0..2047
            int r  = j >> 5;            // row 0..63
            int c4 = j & 31;
            int node = node0 + r;
            if (node < N_NODES) A4[(size_t)node * 32 + c4] = z;
        }
    }

    // ---- Compute: 16 k-steps x 8 n-tiles x 3 split terms ----
    float acc[8][4];
    #pragma unroll
    for (int j = 0; j < 8; j++)
        #pragma unroll
        for (int c = 0; c < 4; c++) acc[j][c] = 0.f;

    #pragma unroll 4
    for (int ks = 0; ks < 16; ks++) {
        uint32_t ah[4], al[4];
        int wA = (m0 + grp) * 132 + ks * 8;
        ah[0] = smem[SX_H + wA + qp];
        ah[1] = smem[SX_H + wA + 1056 + qp];      // +8 rows
        ah[2] = smem[SX_H + wA + 4 + qp];         // +8 k
        ah[3] = smem[SX_H + wA + 1060 + qp];
        al[0] = smem[SX_L + wA + qp];
        al[1] = smem[SX_L + wA + 1056 + qp];
        al[2] = smem[SX_L + wA + 4 + qp];
        al[3] = smem[SX_L + wA + 1060 + qp];

        #pragma unroll
        for (int j = 0; j < 8; j++) {
            int wB = (n0 + j * 8 + grp) * 132 + ks * 8;
            uint32_t bh[2], bl[2];
            bh[0] = smem[SW_H + wB + qp];
            bh[1] = smem[SW_H + wB + 4 + qp];
            bl[0] = smem[SW_L + wB + qp];
            bl[1] = smem[SW_L + wB + 4 + qp];
            mma_bf16(acc[j], ah, bh);
            mma_bf16(acc[j], ah, bl);
            mma_bf16(acc[j], al, bh);
        }
    }

    // ---- Epilogue: + bias, store fp32 ----
    int row_a = node0 + m0 + grp;
    int row_b = row_a + 8;
    #pragma unroll
    for (int j = 0; j < 8; j++) {
        int col = n0 + j * 8 + qp * 2;
        float2 bv = *reinterpret_cast<const float2*>(bias + col);
        if (row_a < N_NODES) {
            float2 o = make_float2(acc[j][0] + bv.x, acc[j][1] + bv.y);
            *reinterpret_cast<float2*>(out + (size_t)row_a * D_OUT + col) = o;
        }
        if (row_b < N_NODES) {
            float2 o = make_float2(acc[j][2] + bv.x, acc[j][3] + bv.y);
            *reinterpret_cast<float2*>(out + (size_t)row_b * D_OUT + col) = o;
        }
    }
}

// ---------------------------------------------------------------------------
extern "C" void kernel_launch(void* const* d_in, const int* in_sizes, int n_in,
                              void* d_out, int out_size) {
    const float* vdata   = (const float*)d_in[0];
    const float* edata_a = (const float*)d_in[1];
    const float* edata_b = (const float*)d_in[2];
    const int*   conn_a  = (const int*)d_in[3];
    const int*   conn_b  = (const int*)d_in[4];
    const float* W       = (const float*)d_in[5];
    const float* bias    = (const float*)d_in[6];
    float*       out     = (float*)d_out;

    // 0) W split/transpose image
    prep_w_kernel<<<(D_IN * D_OUT + 255) / 256, 256>>>(W);

    // 1) fused scatter for both edge types (receivers = conn[1, :])
    {
        int total = 2 * N_EDGES * 16;              // 25.6M threads
        scatter2_kernel<<<total / 256, 256>>>(edata_a, conn_a + N_EDGES,
                                              edata_b, conn_b + N_EDGES);
    }
    // 2) HMMA GEMM + bias (also re-zeroes g_x for the next replay)
    {
        size_t smem_bytes = SMEM_WORDS * sizeof(uint32_t);   // 202752
        cudaFuncSetAttribute(gemm_mma_kernel,
                             cudaFuncAttributeMaxDynamicSharedMemorySize,
                             (int)smem_bytes);
        int blocks = (N_NODES + 63) / 64;
        gemm_mma_kernel<<<blocks, 256, smem_bytes>>>(vdata, bias, out);
    }
}

// round 6
// speedup vs baseline: 1.2832x; 1.2832x over previous
#include <cuda_runtime.h>
#include <cuda_bf16.h>
#include <cstdint>

#define N_NODES 100000
#define N_EDGES 800000
#define D_IN    256
#define D_OUT   128

#define KPAD    264
#define W_IMG_HALF  67584
#define W_IMG_TOTAL 135168
#define TILES   1563            // ceil(100000 / 64)
#define GRID_P  148             // persistent CTAs

// Aggregation buffer: [N_NODES][128] = [agg_a(0:64) | agg_b(64:128)].
// BSS-zeroed at load; gemm re-zeroes each tile after consuming it.
__device__ __align__(16) float g_x[(size_t)N_NODES * 128];

// W^T split images: [n=128][k=264(padded)] bf16, hi at 0, lo at W_IMG_HALF
__device__ __align__(16) unsigned char g_wt[W_IMG_TOTAL];

// ---------------------------------------------------------------------------
// Kernel 0: split W into bf16 hi/lo, transposed into padded image.
// ---------------------------------------------------------------------------
__global__ void prep_w_kernel(const float* __restrict__ W) {
    int idx = blockIdx.x * blockDim.x + threadIdx.x;
    if (idx >= D_IN * D_OUT) return;
    int n = idx & 127;
    int k = idx >> 7;
    float w = W[k * D_OUT + n];
    __nv_bfloat16 h = __float2bfloat16_rn(w);
    __nv_bfloat16 l = __float2bfloat16_rn(w - __bfloat162float(h));
    uint32_t off = (uint32_t)n * (KPAD * 2) + (uint32_t)k * 2;
    *(__nv_bfloat16*)(g_wt + off)              = h;
    *(__nv_bfloat16*)(g_wt + W_IMG_HALF + off) = l;
}

// ---------------------------------------------------------------------------
// Kernel 1: fused scatter-add for both edge types (red.global.add.v4.f32)
// ---------------------------------------------------------------------------
__global__ void scatter2_kernel(const float* __restrict__ edata_a,
                                const int* __restrict__ recv_a,
                                const float* __restrict__ edata_b,
                                const int* __restrict__ recv_b) {
    int idx = blockIdx.x * blockDim.x + threadIdx.x;
    const int half = N_EDGES * 16;
    bool isB = idx >= half;
    int i = isB ? idx - half : idx;
    const float* e  = isB ? edata_b : edata_a;
    const int*   rv = isB ? recv_b  : recv_a;
    int edge = i >> 4;
    int q    = i & 15;
    float4 v = reinterpret_cast<const float4*>(e)[(size_t)edge * 16 + q];
    int r = rv[edge];
    float* dst = g_x + (size_t)r * 128 + (isB ? 64 : 0) + q * 4;
    asm volatile("red.global.add.v4.f32 [%0], {%1, %2, %3, %4};"
                 :: "l"(dst), "f"(v.x), "f"(v.y), "f"(v.z), "f"(v.w)
                 : "memory");
}

// ---------------------------------------------------------------------------
__device__ __forceinline__ void mma_bf16(float* d, const uint32_t* a,
                                         const uint32_t* b) {
    asm volatile(
        "mma.sync.aligned.m16n8k16.row.col.f32.bf16.bf16.f32 "
        "{%0,%1,%2,%3}, {%4,%5,%6,%7}, {%8,%9}, {%0,%1,%2,%3};"
        : "+f"(d[0]), "+f"(d[1]), "+f"(d[2]), "+f"(d[3])
        : "r"(a[0]), "r"(a[1]), "r"(a[2]), "r"(a[3]),
          "r"(b[0]), "r"(b[1]));
}

// SMEM layout (uint32 words)
#define SW_H 0
#define SW_L 16896
#define SX_H 33792
#define SX_L 42240
#define SMEM_WORDS 50688     // 202752 bytes

// ---------------------------------------------------------------------------
// Kernel 2: persistent split-bf16 HMMA GEMM. 512 threads / 16 warps.
// W image staged ONCE per CTA; tiles of 64 nodes strided across GRID_P CTAs.
// Next tile's x loads prefetched into registers during compute.
// ---------------------------------------------------------------------------
__global__ __launch_bounds__(512, 1)
void gemm_mma_kernel(const float* __restrict__ vdata,
                     const float* __restrict__ bias,
                     float* __restrict__ out) {
    extern __shared__ uint32_t smem[];
    const int tid  = threadIdx.x;
    const int wid  = tid >> 5;
    const int lane = tid & 31;
    const int grp  = lane >> 2;
    const int qp   = lane & 3;

    const int m0 = (wid & 3) * 16;    // warp M band (of 64)
    const int n0 = (wid >> 2) * 32;   // warp N quarter (of 128)

    // ---- Stage W^T image once (hi+lo, 8448 uint4) ----
    {
        const uint4* src = reinterpret_cast<const uint4*>(g_wt);
        uint4* dst = reinterpret_cast<uint4*>(smem);
        #pragma unroll
        for (int i = 0; i < 17; i++) {
            int j = i * 512 + tid;
            if (j < 8448) dst[j] = src[j];
        }
    }

    // bias fragments (tile-invariant)
    float2 bv[4];
    #pragma unroll
    for (int j = 0; j < 4; j++)
        bv[j] = *reinterpret_cast<const float2*>(bias + n0 + j * 8 + qp * 2);

    const float4* A4 = reinterpret_cast<const float4*>(g_x);
    const float4* V4 = reinterpret_cast<const float4*>(vdata);

    int t = blockIdx.x;
    float4 xr[8];

    // prefetch first tile
    if (t < TILES) {
        int node0 = t * 64;
        #pragma unroll
        for (int i = 0; i < 8; i++) {
            int j = i * 512 + tid;
            int r = j >> 6, c4 = j & 63;
            int node = node0 + r;
            float4 v = make_float4(0.f, 0.f, 0.f, 0.f);
            if (node < N_NODES)
                v = (c4 < 32) ? A4[(size_t)node * 32 + c4]
                              : V4[(size_t)node * 32 + (c4 - 32)];
            xr[i] = v;
        }
    }

    while (t < TILES) {
        const int node0 = t * 64;

        // ---- convert regs -> smem bf16 hi/lo; re-zero consumed g_x region ----
        #pragma unroll
        for (int i = 0; i < 8; i++) {
            int j = i * 512 + tid;
            int r = j >> 6, c4 = j & 63;
            float4 v = xr[i];
            __nv_bfloat16 h0 = __float2bfloat16_rn(v.x);
            __nv_bfloat16 h1 = __float2bfloat16_rn(v.y);
            __nv_bfloat16 h2 = __float2bfloat16_rn(v.z);
            __nv_bfloat16 h3 = __float2bfloat16_rn(v.w);
            __nv_bfloat16 l0 = __float2bfloat16_rn(v.x - __bfloat162float(h0));
            __nv_bfloat16 l1 = __float2bfloat16_rn(v.y - __bfloat162float(h1));
            __nv_bfloat16 l2 = __float2bfloat16_rn(v.z - __bfloat162float(h2));
            __nv_bfloat16 l3 = __float2bfloat16_rn(v.w - __bfloat162float(h3));
            uint32_t hi01 = ((uint32_t)__bfloat16_as_ushort(h1) << 16) | __bfloat16_as_ushort(h0);
            uint32_t hi23 = ((uint32_t)__bfloat16_as_ushort(h3) << 16) | __bfloat16_as_ushort(h2);
            uint32_t lo01 = ((uint32_t)__bfloat16_as_ushort(l1) << 16) | __bfloat16_as_ushort(l0);
            uint32_t lo23 = ((uint32_t)__bfloat16_as_ushort(l3) << 16) | __bfloat16_as_ushort(l2);
            int wbase = r * 132 + c4 * 2;
            smem[SX_H + wbase]     = hi01;
            smem[SX_H + wbase + 1] = hi23;
            smem[SX_L + wbase]     = lo01;
            smem[SX_L + wbase + 1] = lo23;
            if (c4 < 32) {
                int node = node0 + r;
                if (node < N_NODES)
                    reinterpret_cast<float4*>(g_x)[(size_t)node * 32 + c4] =
                        make_float4(0.f, 0.f, 0.f, 0.f);
            }
        }
        __syncthreads();

        // ---- prefetch next tile while computing this one ----
        int tn = t + GRID_P;
        if (tn < TILES) {
            int nn0 = tn * 64;
            #pragma unroll
            for (int i = 0; i < 8; i++) {
                int j = i * 512 + tid;
                int r = j >> 6, c4 = j & 63;
                int node = nn0 + r;
                float4 v = make_float4(0.f, 0.f, 0.f, 0.f);
                if (node < N_NODES)
                    v = (c4 < 32) ? A4[(size_t)node * 32 + c4]
                                  : V4[(size_t)node * 32 + (c4 - 32)];
                xr[i] = v;
            }
        }

        // ---- compute: 16 k-steps x 4 n-tiles x 3 split terms ----
        float acc[4][4];
        #pragma unroll
        for (int j = 0; j < 4; j++)
            #pragma unroll
            for (int c = 0; c < 4; c++) acc[j][c] = 0.f;

        #pragma unroll 4
        for (int ks = 0; ks < 16; ks++) {
            uint32_t ah[4], al[4];
            int wA = (m0 + grp) * 132 + ks * 8;
            ah[0] = smem[SX_H + wA + qp];
            ah[1] = smem[SX_H + wA + 1056 + qp];
            ah[2] = smem[SX_H + wA + 4 + qp];
            ah[3] = smem[SX_H + wA + 1060 + qp];
            al[0] = smem[SX_L + wA + qp];
            al[1] = smem[SX_L + wA + 1056 + qp];
            al[2] = smem[SX_L + wA + 4 + qp];
            al[3] = smem[SX_L + wA + 1060 + qp];

            #pragma unroll
            for (int j = 0; j < 4; j++) {
                int wB = (n0 + j * 8 + grp) * 132 + ks * 8;
                uint32_t bh[2], bl[2];
                bh[0] = smem[SW_H + wB + qp];
                bh[1] = smem[SW_H + wB + 4 + qp];
                bl[0] = smem[SW_L + wB + qp];
                bl[1] = smem[SW_L + wB + 4 + qp];
                mma_bf16(acc[j], ah, bh);
                mma_bf16(acc[j], ah, bl);
                mma_bf16(acc[j], al, bh);
            }
        }

        // ---- epilogue ----
        int row_a = node0 + m0 + grp;
        int row_b = row_a + 8;
        #pragma unroll
        for (int j = 0; j < 4; j++) {
            int col = n0 + j * 8 + qp * 2;
            if (row_a < N_NODES) {
                float2 o = make_float2(acc[j][0] + bv[j].x, acc[j][1] + bv[j].y);
                *reinterpret_cast<float2*>(out + (size_t)row_a * D_OUT + col) = o;
            }
            if (row_b < N_NODES) {
                float2 o = make_float2(acc[j][2] + bv[j].x, acc[j][3] + bv[j].y);
                *reinterpret_cast<float2*>(out + (size_t)row_b * D_OUT + col) = o;
            }
        }
        __syncthreads();   // x smem reuse barrier
        t = tn;
    }
}

// ---------------------------------------------------------------------------
extern "C" void kernel_launch(void* const* d_in, const int* in_sizes, int n_in,
                              void* d_out, int out_size) {
    const float* vdata   = (const float*)d_in[0];
    const float* edata_a = (const float*)d_in[1];
    const float* edata_b = (const float*)d_in[2];
    const int*   conn_a  = (const int*)d_in[3];
    const int*   conn_b  = (const int*)d_in[4];
    const float* W       = (const float*)d_in[5];
    const float* bias    = (const float*)d_in[6];
    float*       out     = (float*)d_out;

    prep_w_kernel<<<(D_IN * D_OUT + 255) / 256, 256>>>(W);

    {
        int total = 2 * N_EDGES * 16;
        scatter2_kernel<<<total / 256, 256>>>(edata_a, conn_a + N_EDGES,
                                              edata_b, conn_b + N_EDGES);
    }
    {
        size_t smem_bytes = SMEM_WORDS * sizeof(uint32_t);   // 202752
        cudaFuncSetAttribute(gemm_mma_kernel,
                             cudaFuncAttributeMaxDynamicSharedMemorySize,
                             (int)smem_bytes);
        gemm_mma_kernel<<<GRID_P, 512, smem_bytes>>>(vdata, bias, out);
    }
}

// round 7
// speedup vs baseline: 1.3471x; 1.0498x over previous
#include <cuda_runtime.h>
#include <cuda_bf16.h>
#include <cstdint>

#define N_NODES 100000
#define N_EDGES 800000
#define D_IN    256
#define D_OUT   128

#define KPADW   268              // padded k-stride in words (268%32=12 -> conflict-free)
#define TILES   1563             // ceil(100000 / 64)
#define GRID_P  148              // persistent CTAs
#define SCAT_BLOCKS 50000        // N_EDGES*16/256

// Aggregation buffer: [N_NODES][128] = [agg_a(0:64) | agg_b(64:128)].
// BSS-zeroed at load; gemm re-zeroes each tile after consuming it.
__device__ __align__(16) float g_x[(size_t)N_NODES * 128];

// W^T tf32 image: [n=128][k=268 padded] as u32 (tf32-rounded fp32 bits)
__device__ __align__(16) uint32_t g_wt[128 * KPADW];

__device__ __forceinline__ uint32_t f2tf32(float f) {
    uint32_t u;
    asm("cvt.rna.tf32.f32 %0, %1;" : "=r"(u) : "f"(f));
    return u;
}

// ---------------------------------------------------------------------------
// Kernel 1: fused scatter-add (both edge types per thread) + W prep blocks.
// ---------------------------------------------------------------------------
__global__ void scatter_prep_kernel(const float* __restrict__ edata_a,
                                    const int* __restrict__ recv_a,
                                    const float* __restrict__ edata_b,
                                    const int* __restrict__ recv_b,
                                    const float* __restrict__ W) {
    if (blockIdx.x >= SCAT_BLOCKS) {
        // ---- prep W^T tf32 image ----
        int idx = (blockIdx.x - SCAT_BLOCKS) * 256 + threadIdx.x;
        if (idx < D_IN * D_OUT) {
            int n = idx & 127;
            int k = idx >> 7;
            g_wt[n * KPADW + k] = f2tf32(W[k * D_OUT + n]);
        }
        return;
    }
    int idx = blockIdx.x * 256 + threadIdx.x;      // 0 .. 12.8M-1
    int edge = idx >> 4;
    int q    = idx & 15;
    float4 va = reinterpret_cast<const float4*>(edata_a)[(size_t)edge * 16 + q];
    float4 vb = reinterpret_cast<const float4*>(edata_b)[(size_t)edge * 16 + q];
    int ra = recv_a[edge];
    int rb = recv_b[edge];
    float* da = g_x + (size_t)ra * 128 + q * 4;
    float* db = g_x + (size_t)rb * 128 + 64 + q * 4;
    asm volatile("red.global.add.v4.f32 [%0], {%1, %2, %3, %4};"
                 :: "l"(da), "f"(va.x), "f"(va.y), "f"(va.z), "f"(va.w) : "memory");
    asm volatile("red.global.add.v4.f32 [%0], {%1, %2, %3, %4};"
                 :: "l"(db), "f"(vb.x), "f"(vb.y), "f"(vb.z), "f"(vb.w) : "memory");
}

// ---------------------------------------------------------------------------
__device__ __forceinline__ void mma_tf32(float* d, const uint32_t* a,
                                         const uint32_t* b) {
    asm volatile(
        "mma.sync.aligned.m16n8k8.row.col.f32.tf32.tf32.f32 "
        "{%0,%1,%2,%3}, {%4,%5,%6,%7}, {%8,%9}, {%0,%1,%2,%3};"
        : "+f"(d[0]), "+f"(d[1]), "+f"(d[2]), "+f"(d[3])
        : "r"(a[0]), "r"(a[1]), "r"(a[2]), "r"(a[3]),
          "r"(b[0]), "r"(b[1]));
}

// SMEM layout (uint32 words): sW [0, 34304), sX [34304, 51456)
#define SW_BASE 0
#define SX_BASE 34304
#define SMEM_WORDS 51456       // 205824 bytes

// ---------------------------------------------------------------------------
// Kernel 2: persistent TF32 HMMA GEMM. 512 threads / 16 warps.
// W image staged once per CTA; 64-node tiles strided across GRID_P CTAs;
// next tile's x prefetched into registers during compute.
// ---------------------------------------------------------------------------
__global__ __launch_bounds__(512, 1)
void gemm_mma_kernel(const float* __restrict__ vdata,
                     const float* __restrict__ bias,
                     float* __restrict__ out) {
    extern __shared__ uint32_t smem[];
    const int tid  = threadIdx.x;
    const int wid  = tid >> 5;
    const int lane = tid & 31;
    const int grp  = lane >> 2;
    const int qp   = lane & 3;

    const int m0 = (wid & 3) * 16;    // warp M band (of 64)
    const int n0 = (wid >> 2) * 32;   // warp N quarter (of 128)

    // ---- Stage W^T tf32 image once (137216B = 8576 uint4) ----
    {
        const uint4* src = reinterpret_cast<const uint4*>(g_wt);
        uint4* dst = reinterpret_cast<uint4*>(smem + SW_BASE);
        #pragma unroll
        for (int i = 0; i < 17; i++) {
            int j = i * 512 + tid;
            if (j < 128 * KPADW / 4) dst[j] = src[j];
        }
    }

    // bias fragments (tile-invariant)
    float2 bv[4];
    #pragma unroll
    for (int j = 0; j < 4; j++)
        bv[j] = *reinterpret_cast<const float2*>(bias + n0 + j * 8 + qp * 2);

    const float4* A4 = reinterpret_cast<const float4*>(g_x);
    const float4* V4 = reinterpret_cast<const float4*>(vdata);

    int t = blockIdx.x;
    float4 xr[8];

    // prefetch first tile
    if (t < TILES) {
        int node0 = t * 64;
        #pragma unroll
        for (int i = 0; i < 8; i++) {
            int j = i * 512 + tid;
            int r = j >> 6, c4 = j & 63;
            int node = node0 + r;
            float4 v = make_float4(0.f, 0.f, 0.f, 0.f);
            if (node < N_NODES)
                v = (c4 < 32) ? A4[(size_t)node * 32 + c4]
                              : V4[(size_t)node * 32 + (c4 - 32)];
            xr[i] = v;
        }
    }

    while (t < TILES) {
        const int node0 = t * 64;

        // ---- convert regs -> smem tf32; re-zero consumed g_x region ----
        #pragma unroll
        for (int i = 0; i < 8; i++) {
            int j = i * 512 + tid;
            int r = j >> 6, c4 = j & 63;
            float4 v = xr[i];
            int wbase = SX_BASE + r * KPADW + c4 * 4;
            smem[wbase + 0] = f2tf32(v.x);
            smem[wbase + 1] = f2tf32(v.y);
            smem[wbase + 2] = f2tf32(v.z);
            smem[wbase + 3] = f2tf32(v.w);
            if (c4 < 32) {
                int node = node0 + r;
                if (node < N_NODES)
                    reinterpret_cast<float4*>(g_x)[(size_t)node * 32 + c4] =
                        make_float4(0.f, 0.f, 0.f, 0.f);
            }
        }
        __syncthreads();

        // ---- prefetch next tile during compute ----
        int tn = t + GRID_P;
        if (tn < TILES) {
            int nn0 = tn * 64;
            #pragma unroll
            for (int i = 0; i < 8; i++) {
                int j = i * 512 + tid;
                int r = j >> 6, c4 = j & 63;
                int node = nn0 + r;
                float4 v = make_float4(0.f, 0.f, 0.f, 0.f);
                if (node < N_NODES)
                    v = (c4 < 32) ? A4[(size_t)node * 32 + c4]
                                  : V4[(size_t)node * 32 + (c4 - 32)];
                xr[i] = v;
            }
        }

        // ---- compute: 32 k-steps (k=8) x 4 n-tiles, single tf32 pass ----
        float acc[4][4];
        #pragma unroll
        for (int j = 0; j < 4; j++)
            #pragma unroll
            for (int c = 0; c < 4; c++) acc[j][c] = 0.f;

        #pragma unroll 4
        for (int ks = 0; ks < 32; ks++) {
            uint32_t a[4];
            int wA = SX_BASE + (m0 + grp) * KPADW + ks * 8;
            a[0] = smem[wA + qp];
            a[1] = smem[wA + 8 * KPADW + qp];
            a[2] = smem[wA + 4 + qp];
            a[3] = smem[wA + 8 * KPADW + 4 + qp];

            #pragma unroll
            for (int j = 0; j < 4; j++) {
                int wB = SW_BASE + (n0 + j * 8 + grp) * KPADW + ks * 8;
                uint32_t b[2];
                b[0] = smem[wB + qp];
                b[1] = smem[wB + 4 + qp];
                mma_tf32(acc[j], a, b);
            }
        }

        // ---- epilogue ----
        int row_a = node0 + m0 + grp;
        int row_b = row_a + 8;
        #pragma unroll
        for (int j = 0; j < 4; j++) {
            int col = n0 + j * 8 + qp * 2;
            if (row_a < N_NODES) {
                float2 o = make_float2(acc[j][0] + bv[j].x, acc[j][1] + bv[j].y);
                *reinterpret_cast<float2*>(out + (size_t)row_a * D_OUT + col) = o;
            }
            if (row_b < N_NODES) {
                float2 o = make_float2(acc[j][2] + bv[j].x, acc[j][3] + bv[j].y);
                *reinterpret_cast<float2*>(out + (size_t)row_b * D_OUT + col) = o;
            }
        }
        __syncthreads();   // x smem reuse barrier
        t = tn;
    }
}

// ---------------------------------------------------------------------------
extern "C" void kernel_launch(void* const* d_in, const int* in_sizes, int n_in,
                              void* d_out, int out_size) {
    const float* vdata   = (const float*)d_in[0];
    const float* edata_a = (const float*)d_in[1];
    const float* edata_b = (const float*)d_in[2];
    const int*   conn_a  = (const int*)d_in[3];
    const int*   conn_b  = (const int*)d_in[4];
    const float* W       = (const float*)d_in[5];
    const float* bias    = (const float*)d_in[6];
    float*       out     = (float*)d_out;

    // 1) fused scatter (both edge types) + W prep (extra blocks)
    scatter_prep_kernel<<<SCAT_BLOCKS + 128, 256>>>(
        edata_a, conn_a + N_EDGES, edata_b, conn_b + N_EDGES, W);

    // 2) persistent TF32 GEMM + bias (re-zeroes g_x for next replay)
    {
        size_t smem_bytes = SMEM_WORDS * sizeof(uint32_t);   // 205824
        cudaFuncSetAttribute(gemm_mma_kernel,
                             cudaFuncAttributeMaxDynamicSharedMemorySize,
                             (int)smem_bytes);
        gemm_mma_kernel<<<GRID_P, 512, smem_bytes>>>(vdata, bias, out);
    }
}